// round 2
// baseline (speedup 1.0000x reference)
#include <cuda_runtime.h>
#include <cstdint>

// Problem constants
#define BB    4
#define SS    2048
#define DD    1024
#define HH    16
#define DEPTH 64
#define MTOT  (BB * SS)            // 8192 rows for the projections

// Scratch (allocation-free rule: __device__ globals)
__device__ float g_q  [(size_t)BB * HH * SS * DEPTH];   // [B,H,S,64]
__device__ float g_k  [(size_t)BB * HH * SS * DEPTH];
__device__ float g_v  [(size_t)BB * HH * SS * DEPTH];
__device__ float g_ctx[(size_t)BB * SS * DD];           // [B,S,D] concat layout
__device__ float g_attn_fb[(size_t)BB * HH * SS * SS];  // fallback if attn not in d_out

// ---------------------------------------------------------------------------
// Generic C[m,n] = sum_k A[m,k] * W[n,k] + bias[n]
// BM=BN=128, BK=8, 256 threads, 8x8 micro-tile.
// head_layout: write into [B,H,S,DEPTH] instead of [M,N].
// ---------------------------------------------------------------------------
__global__ __launch_bounds__(256) void gemm_bias_abt(
    const float* __restrict__ A, const float* __restrict__ W,
    const float* __restrict__ bias, float* __restrict__ C,
    int M, int N, int K, int head_layout)
{
    __shared__ float As[8][128];
    __shared__ float Bs[8][128];

    const int t  = threadIdx.x;
    const int m0 = blockIdx.y * 128;
    const int n0 = blockIdx.x * 128;
    const int lr = t >> 1;            // loader row 0..127
    const int lk = (t & 1) * 4;       // loader k-offset {0,4}
    const int ty = t >> 4;            // 0..15
    const int tx = t & 15;            // 0..15

    float acc[8][8];
#pragma unroll
    for (int i = 0; i < 8; i++)
#pragma unroll
        for (int j = 0; j < 8; j++) acc[i][j] = 0.f;

    for (int k0 = 0; k0 < K; k0 += 8) {
        float4 av = *(const float4*)&A[(size_t)(m0 + lr) * K + k0 + lk];
        float4 bv = *(const float4*)&W[(size_t)(n0 + lr) * K + k0 + lk];
        As[lk + 0][lr] = av.x; As[lk + 1][lr] = av.y;
        As[lk + 2][lr] = av.z; As[lk + 3][lr] = av.w;
        Bs[lk + 0][lr] = bv.x; Bs[lk + 1][lr] = bv.y;
        Bs[lk + 2][lr] = bv.z; Bs[lk + 3][lr] = bv.w;
        __syncthreads();
#pragma unroll
        for (int kk = 0; kk < 8; kk++) {
            float a[8], b[8];
            *(float4*)&a[0] = *(const float4*)&As[kk][ty * 8];
            *(float4*)&a[4] = *(const float4*)&As[kk][ty * 8 + 4];
            *(float4*)&b[0] = *(const float4*)&Bs[kk][tx * 8];
            *(float4*)&b[4] = *(const float4*)&Bs[kk][tx * 8 + 4];
#pragma unroll
            for (int i = 0; i < 8; i++)
#pragma unroll
                for (int j = 0; j < 8; j++)
                    acc[i][j] = fmaf(a[i], b[j], acc[i][j]);
        }
        __syncthreads();
    }

#pragma unroll
    for (int i = 0; i < 8; i++) {
        const int m = m0 + ty * 8 + i;
#pragma unroll
        for (int j = 0; j < 8; j++) {
            const int n = n0 + tx * 8 + j;
            const float v = acc[i][j] + bias[n];
            if (head_layout) {
                const int b  = m / SS, s_ = m % SS;
                const int h  = n / DEPTH, dp = n % DEPTH;
                C[(((size_t)(b * HH + h)) * SS + s_) * DEPTH + dp] = v;
            } else {
                C[(size_t)m * N + n] = v;
            }
        }
    }
}

// ---------------------------------------------------------------------------
// logits[bh, q, k] = (k<=q) ? dot(Q[bh,q], K[bh,k]) / 8 : 0
// 128x128 tiles in (q,k); fully-masked tiles only zero-fill.
// ---------------------------------------------------------------------------
__global__ __launch_bounds__(256) void attn_logits(
    const float* __restrict__ Qh, const float* __restrict__ Kh,
    float* __restrict__ attn)
{
    const int bh = blockIdx.z;
    const int tq = blockIdx.y;
    const int tk = blockIdx.x;
    const int t  = threadIdx.x;
    const int ty = t >> 4, tx = t & 15;

    const size_t abase = ((size_t)bh * SS + (size_t)tq * 128) * SS + (size_t)tk * 128;

    if (tk > tq) {  // tile entirely above diagonal -> exact zeros
#pragma unroll
        for (int i = 0; i < 8; i++)
#pragma unroll
            for (int j = 0; j < 8; j++)
                attn[abase + (size_t)(ty * 8 + i) * SS + tx * 8 + j] = 0.f;
        return;
    }

    __shared__ float Qs[16][128];
    __shared__ float Ks[16][128];

    const float* Qb = Qh + ((size_t)bh * SS + (size_t)tq * 128) * DEPTH;
    const float* Kb = Kh + ((size_t)bh * SS + (size_t)tk * 128) * DEPTH;

    float acc[8][8];
#pragma unroll
    for (int i = 0; i < 8; i++)
#pragma unroll
        for (int j = 0; j < 8; j++) acc[i][j] = 0.f;

    for (int k0 = 0; k0 < DEPTH; k0 += 16) {
#pragma unroll
        for (int j = 0; j < 2; j++) {
            const int f = t * 2 + j;
            const int row = f >> 2;          // 0..127 (4 float4 per row)
            const int kq  = (f & 3) * 4;
            float4 qv = *(const float4*)&Qb[(size_t)row * DEPTH + k0 + kq];
            Qs[kq + 0][row] = qv.x; Qs[kq + 1][row] = qv.y;
            Qs[kq + 2][row] = qv.z; Qs[kq + 3][row] = qv.w;
            float4 kv = *(const float4*)&Kb[(size_t)row * DEPTH + k0 + kq];
            Ks[kq + 0][row] = kv.x; Ks[kq + 1][row] = kv.y;
            Ks[kq + 2][row] = kv.z; Ks[kq + 3][row] = kv.w;
        }
        __syncthreads();
#pragma unroll
        for (int kk = 0; kk < 16; kk++) {
            float a[8], b[8];
            *(float4*)&a[0] = *(const float4*)&Qs[kk][ty * 8];
            *(float4*)&a[4] = *(const float4*)&Qs[kk][ty * 8 + 4];
            *(float4*)&b[0] = *(const float4*)&Ks[kk][tx * 8];
            *(float4*)&b[4] = *(const float4*)&Ks[kk][tx * 8 + 4];
#pragma unroll
            for (int i = 0; i < 8; i++)
#pragma unroll
                for (int j = 0; j < 8; j++)
                    acc[i][j] = fmaf(a[i], b[j], acc[i][j]);
        }
        __syncthreads();
    }

    const int qg0 = tq * 128, kg0 = tk * 128;
#pragma unroll
    for (int i = 0; i < 8; i++) {
        const int qg = qg0 + ty * 8 + i;
#pragma unroll
        for (int j = 0; j < 8; j++) {
            const int kg = kg0 + tx * 8 + j;
            attn[abase + (size_t)(ty * 8 + i) * SS + tx * 8 + j] =
                (kg <= qg) ? acc[i][j] * 0.125f : 0.f;
        }
    }
}

// ---------------------------------------------------------------------------
// Row softmax over the first (q+1) entries (masked tail is already 0).
// One block (256 threads) per row; B*H*S rows.
// ---------------------------------------------------------------------------
__global__ __launch_bounds__(256) void softmax_rows(float* __restrict__ attn)
{
    const size_t row = blockIdx.x;
    const int q = (int)(row % SS);
    const int n = q + 1;
    float* p = attn + row * SS;
    const int t = threadIdx.x;

    __shared__ float redm[8];
    __shared__ float reds[8];

    float m = -1e30f;
    for (int i = t; i < n; i += 256) m = fmaxf(m, p[i]);
#pragma unroll
    for (int o = 16; o; o >>= 1) m = fmaxf(m, __shfl_xor_sync(0xffffffffu, m, o));
    if ((t & 31) == 0) redm[t >> 5] = m;
    __syncthreads();
    float bm = redm[0];
#pragma unroll
    for (int w = 1; w < 8; w++) bm = fmaxf(bm, redm[w]);

    float s = 0.f;
    for (int i = t; i < n; i += 256) {
        const float e = __expf(p[i] - bm);
        p[i] = e;
        s += e;
    }
#pragma unroll
    for (int o = 16; o; o >>= 1) s += __shfl_xor_sync(0xffffffffu, s, o);
    if ((t & 31) == 0) reds[t >> 5] = s;
    __syncthreads();
    float bs = reds[0];
#pragma unroll
    for (int w = 1; w < 8; w++) bs += reds[w];
    const float inv = 1.0f / bs;

    for (int i = t; i < n; i += 256) p[i] *= inv;
}

// ---------------------------------------------------------------------------
// ctx[b, q, h*64+c] = sum_k attn[bh,q,k] * V[bh,k,c]
// BM=128 q-rows, N=64 (full head dim), BK=32. 8x4 micro-tile.
// Causality: only k-tiles covering k <= tq*128+127, i.e. kt < (tq+1)*4.
// (attn entries above the diagonal are exactly 0, so full 128-wide coverage
//  of the final partial window is safe.)
// ---------------------------------------------------------------------------
__global__ __launch_bounds__(256) void attn_ctx(
    const float* __restrict__ attn, const float* __restrict__ Vh,
    float* __restrict__ ctx)
{
    const int tq = blockIdx.x;
    const int bh = blockIdx.y;
    const int b  = bh / HH, h = bh % HH;
    const int t  = threadIdx.x;
    const int ty = t >> 4, tx = t & 15;

    __shared__ float At[32][128];
    __shared__ float Vs[32][64];

    const float* arow = attn + ((size_t)bh * SS + (size_t)tq * 128) * SS;
    const float* Vb   = Vh + (size_t)bh * SS * DEPTH;

    float acc[8][4];
#pragma unroll
    for (int i = 0; i < 8; i++)
#pragma unroll
        for (int j = 0; j < 4; j++) acc[i][j] = 0.f;

    const int ktmax = (tq + 1) * 4;   // 32-wide k-tiles needed for causal window
    for (int kt = 0; kt < ktmax; kt++) {
#pragma unroll
        for (int j = 0; j < 4; j++) {           // attn tile 128x32
            const int f   = t * 4 + j;
            const int row = f >> 3;             // 8 float4 per row
            const int kq  = (f & 7) * 4;
            float4 av = *(const float4*)&arow[(size_t)row * SS + kt * 32 + kq];
            At[kq + 0][row] = av.x; At[kq + 1][row] = av.y;
            At[kq + 2][row] = av.z; At[kq + 3][row] = av.w;
        }
#pragma unroll
        for (int j = 0; j < 2; j++) {           // V tile 32x64
            const int f   = t * 2 + j;
            const int row = f >> 4;             // 16 float4 per row
            const int c4  = (f & 15) * 4;
            *(float4*)&Vs[row][c4] =
                *(const float4*)&Vb[(size_t)(kt * 32 + row) * DEPTH + c4];
        }
        __syncthreads();
#pragma unroll
        for (int kk = 0; kk < 32; kk++) {
            float a[8], bv[4];
            *(float4*)&a[0] = *(const float4*)&At[kk][ty * 8];
            *(float4*)&a[4] = *(const float4*)&At[kk][ty * 8 + 4];
            *(float4*)&bv[0] = *(const float4*)&Vs[kk][tx * 4];
#pragma unroll
            for (int i = 0; i < 8; i++)
#pragma unroll
                for (int j = 0; j < 4; j++)
                    acc[i][j] = fmaf(a[i], bv[j], acc[i][j]);
        }
        __syncthreads();
    }

#pragma unroll
    for (int i = 0; i < 8; i++) {
        const int q = tq * 128 + ty * 8 + i;
#pragma unroll
        for (int j = 0; j < 4; j++)
            ctx[((size_t)b * SS + q) * DD + h * DEPTH + tx * 4 + j] = acc[i][j];
    }
}

// ---------------------------------------------------------------------------
extern "C" void kernel_launch(void* const* d_in, const int* in_sizes, int n_in,
                              void* d_out, int out_size)
{
    const float* q    = (const float*)d_in[0];
    const float* k    = (const float*)d_in[1];
    const float* v    = (const float*)d_in[2];
    // d_in[3] = mask (causal; applied analytically)
    const float* wq   = (const float*)d_in[4];
    const float* bq   = (const float*)d_in[5];
    const float* wk   = (const float*)d_in[6];
    const float* bk   = (const float*)d_in[7];
    const float* wv   = (const float*)d_in[8];
    const float* bv   = (const float*)d_in[9];
    const float* wo   = (const float*)d_in[10];
    const float* bo   = (const float*)d_in[11];
    float* out = (float*)d_out;

    float *gq, *gk, *gv, *gctx, *gattn;
    cudaGetSymbolAddress((void**)&gq,   g_q);
    cudaGetSymbolAddress((void**)&gk,   g_k);
    cudaGetSymbolAddress((void**)&gv,   g_v);
    cudaGetSymbolAddress((void**)&gctx, g_ctx);
    cudaGetSymbolAddress((void**)&gattn, g_attn_fb);

    const long long OUT_E = (long long)BB * SS * DD;                 // 8,388,608
    const long long ATT_E = (long long)BB * HH * SS * SS;            // 268,435,456
    float* attn = ((long long)out_size >= OUT_E + ATT_E) ? (out + OUT_E) : gattn;

    const dim3 gproj(DD / 128, MTOT / 128);        // (8, 64)

    gemm_bias_abt<<<gproj, 256>>>(q, wq, bq, gq, MTOT, DD, DD, 1);
    gemm_bias_abt<<<gproj, 256>>>(k, wk, bk, gk, MTOT, DD, DD, 1);
    gemm_bias_abt<<<gproj, 256>>>(v, wv, bv, gv, MTOT, DD, DD, 1);

    attn_logits<<<dim3(SS / 128, SS / 128, BB * HH), 256>>>(gq, gk, attn);
    softmax_rows<<<BB * HH * SS, 256>>>(attn);
    attn_ctx<<<dim3(SS / 128, BB * HH), 256>>>(attn, gv, gctx);

    gemm_bias_abt<<<gproj, 256>>>(gctx, wo, bo, out, MTOT, DD, DD, 0);
}

// round 3
// speedup vs baseline: 2.0902x; 2.0902x over previous
#include <cuda_runtime.h>
#include <cstdint>

// Problem constants
#define BB    4
#define SS    2048
#define DD    1024
#define HH    16
#define DEPTH 64
#define MTOT  (BB * SS)

// Scratch (allocation-free rule: __device__ globals)
__device__ float g_q  [(size_t)BB * HH * SS * DEPTH];
__device__ float g_k  [(size_t)BB * HH * SS * DEPTH];
__device__ float g_v  [(size_t)BB * HH * SS * DEPTH];
__device__ float g_ctx[(size_t)BB * SS * DD];
__device__ float g_attn_fb[(size_t)BB * HH * SS * SS];

// ---------------------------------------------------------------------------
__device__ __forceinline__ uint32_t f2tf(float x) {
    uint32_t r;
    asm("cvt.rna.tf32.f32 %0, %1;" : "=r"(r) : "f"(x));
    return r;
}

__device__ __forceinline__ void mma_tf32(float* c, const uint32_t* a, const uint32_t* b) {
    asm volatile(
        "mma.sync.aligned.m16n8k8.row.col.f32.tf32.tf32.f32 "
        "{%0,%1,%2,%3}, {%4,%5,%6,%7}, {%8,%9}, {%0,%1,%2,%3};"
        : "+f"(c[0]), "+f"(c[1]), "+f"(c[2]), "+f"(c[3])
        : "r"(a[0]), "r"(a[1]), "r"(a[2]), "r"(a[3]), "r"(b[0]), "r"(b[1]));
}

// ---------------------------------------------------------------------------
// C[m,n] = sum_k A[m,k] * W[n,k] + bias[n]   via tf32 mma.
// BM=BN=128, BK=16, 256 threads, 8 warps (2m x 4n), warp tile 64x32.
// head_layout: write into [B,H,S,DEPTH].
// ---------------------------------------------------------------------------
__global__ __launch_bounds__(256) void proj_tf32(
    const float* __restrict__ A, const float* __restrict__ W,
    const float* __restrict__ bias, float* __restrict__ C,
    int M, int N, int K, int head_layout)
{
    __shared__ uint32_t As[128][20];
    __shared__ uint32_t Bs[128][20];

    const int t    = threadIdx.x;
    const int m0   = blockIdx.y * 128;
    const int n0   = blockIdx.x * 128;
    const int wid  = t >> 5, lane = t & 31;
    const int wm   = (wid >> 2) * 64;     // warp m offset (0/64)
    const int wn   = (wid & 3) * 32;      // warp n offset
    const int g    = lane >> 2;           // 0..7
    const int tg   = lane & 3;            // 0..3

    float acc[4][4][4];
#pragma unroll
    for (int i = 0; i < 4; i++)
#pragma unroll
        for (int j = 0; j < 4; j++)
#pragma unroll
            for (int r = 0; r < 4; r++) acc[i][j][r] = 0.f;

    for (int k0 = 0; k0 < K; k0 += 16) {
#pragma unroll
        for (int i = 0; i < 2; i++) {
            const int f   = t * 2 + i;
            const int row = f >> 2;
            const int kq  = (f & 3) * 4;
            float4 av = *(const float4*)&A[(size_t)(m0 + row) * K + k0 + kq];
            uint4 au = make_uint4(f2tf(av.x), f2tf(av.y), f2tf(av.z), f2tf(av.w));
            *(uint4*)&As[row][kq] = au;
            float4 bv = *(const float4*)&W[(size_t)(n0 + row) * K + k0 + kq];
            uint4 bu = make_uint4(f2tf(bv.x), f2tf(bv.y), f2tf(bv.z), f2tf(bv.w));
            *(uint4*)&Bs[row][kq] = bu;
        }
        __syncthreads();

#pragma unroll
        for (int ks = 0; ks < 16; ks += 8) {
            uint32_t a[4][4], b[4][2];
#pragma unroll
            for (int i = 0; i < 4; i++) {
                const int r = wm + i * 16;
                a[i][0] = As[r + g][ks + tg];
                a[i][1] = As[r + g + 8][ks + tg];
                a[i][2] = As[r + g][ks + tg + 4];
                a[i][3] = As[r + g + 8][ks + tg + 4];
            }
#pragma unroll
            for (int j = 0; j < 4; j++) {
                const int n = wn + j * 8;
                b[j][0] = Bs[n + g][ks + tg];
                b[j][1] = Bs[n + g][ks + tg + 4];
            }
#pragma unroll
            for (int i = 0; i < 4; i++)
#pragma unroll
                for (int j = 0; j < 4; j++)
                    mma_tf32(acc[i][j], a[i], b[j]);
        }
        __syncthreads();
    }

#pragma unroll
    for (int i = 0; i < 4; i++) {
#pragma unroll
        for (int j = 0; j < 4; j++) {
            const int n = n0 + wn + j * 8 + 2 * tg;
#pragma unroll
            for (int half = 0; half < 2; half++) {
                const int m = m0 + wm + i * 16 + g + half * 8;
                const float v0 = acc[i][j][half * 2 + 0] + bias[n];
                const float v1 = acc[i][j][half * 2 + 1] + bias[n + 1];
                if (head_layout) {
                    const int bb = m / SS, s_ = m % SS;
                    const int h0 = n / DEPTH, d0 = n % DEPTH;
                    const int h1 = (n + 1) / DEPTH, d1 = (n + 1) % DEPTH;
                    C[(((size_t)(bb * HH + h0)) * SS + s_) * DEPTH + d0] = v0;
                    C[(((size_t)(bb * HH + h1)) * SS + s_) * DEPTH + d1] = v1;
                } else {
                    C[(size_t)m * N + n]     = v0;
                    C[(size_t)m * N + n + 1] = v1;
                }
            }
        }
    }
}

// ---------------------------------------------------------------------------
// logits[bh,q,k] = (k<=q) ? dot(Q,K)/8 : 0   via tf32 mma.  K-dim = DEPTH = 64.
// ---------------------------------------------------------------------------
__global__ __launch_bounds__(256) void attn_logits_tf32(
    const float* __restrict__ Qh, const float* __restrict__ Kh,
    float* __restrict__ attn)
{
    const int bh = blockIdx.z;
    const int tq = blockIdx.y;
    const int tk = blockIdx.x;
    const int t  = threadIdx.x;

    const size_t abase = ((size_t)bh * SS + (size_t)tq * 128) * SS + (size_t)tk * 128;

    if (tk > tq) {  // fully-masked tile -> exact zeros (float4 fill)
        float4 z = make_float4(0.f, 0.f, 0.f, 0.f);
        float* base = attn + abase;
        for (int idx = t; idx < 128 * 32; idx += 256) {
            const int row = idx >> 5, c4 = (idx & 31) * 4;
            *(float4*)&base[(size_t)row * SS + c4] = z;
        }
        return;
    }

    __shared__ uint32_t Qs[128][20];
    __shared__ uint32_t Ks[128][20];

    const float* Qb = Qh + ((size_t)bh * SS + (size_t)tq * 128) * DEPTH;
    const float* Kb = Kh + ((size_t)bh * SS + (size_t)tk * 128) * DEPTH;

    const int wid = t >> 5, lane = t & 31;
    const int wm  = (wid >> 2) * 64;
    const int wn  = (wid & 3) * 32;
    const int g   = lane >> 2, tg = lane & 3;

    float acc[4][4][4];
#pragma unroll
    for (int i = 0; i < 4; i++)
#pragma unroll
        for (int j = 0; j < 4; j++)
#pragma unroll
            for (int r = 0; r < 4; r++) acc[i][j][r] = 0.f;

    for (int k0 = 0; k0 < DEPTH; k0 += 16) {
#pragma unroll
        for (int i = 0; i < 2; i++) {
            const int f   = t * 2 + i;
            const int row = f >> 2;
            const int kq  = (f & 3) * 4;
            float4 qv = *(const float4*)&Qb[(size_t)row * DEPTH + k0 + kq];
            // fold 1/8 scale into Q (exact power of 2, no extra rounding)
            uint4 qu = make_uint4(f2tf(qv.x * 0.125f), f2tf(qv.y * 0.125f),
                                  f2tf(qv.z * 0.125f), f2tf(qv.w * 0.125f));
            *(uint4*)&Qs[row][kq] = qu;
            float4 kv = *(const float4*)&Kb[(size_t)row * DEPTH + k0 + kq];
            uint4 ku = make_uint4(f2tf(kv.x), f2tf(kv.y), f2tf(kv.z), f2tf(kv.w));
            *(uint4*)&Ks[row][kq] = ku;
        }
        __syncthreads();

#pragma unroll
        for (int ks = 0; ks < 16; ks += 8) {
            uint32_t a[4][4], b[4][2];
#pragma unroll
            for (int i = 0; i < 4; i++) {
                const int r = wm + i * 16;
                a[i][0] = Qs[r + g][ks + tg];
                a[i][1] = Qs[r + g + 8][ks + tg];
                a[i][2] = Qs[r + g][ks + tg + 4];
                a[i][3] = Qs[r + g + 8][ks + tg + 4];
            }
#pragma unroll
            for (int j = 0; j < 4; j++) {
                const int n = wn + j * 8;
                b[j][0] = Ks[n + g][ks + tg];
                b[j][1] = Ks[n + g][ks + tg + 4];
            }
#pragma unroll
            for (int i = 0; i < 4; i++)
#pragma unroll
                for (int j = 0; j < 4; j++)
                    mma_tf32(acc[i][j], a[i], b[j]);
        }
        __syncthreads();
    }

    const int qg0 = tq * 128, kg0 = tk * 128;
#pragma unroll
    for (int i = 0; i < 4; i++) {
#pragma unroll
        for (int j = 0; j < 4; j++) {
            const int kn = wn + j * 8 + 2 * tg;
#pragma unroll
            for (int half = 0; half < 2; half++) {
                const int qm = wm + i * 16 + g + half * 8;
                const int qg = qg0 + qm;
                const float v0 = (kg0 + kn     <= qg) ? acc[i][j][half * 2 + 0] : 0.f;
                const float v1 = (kg0 + kn + 1 <= qg) ? acc[i][j][half * 2 + 1] : 0.f;
                attn[abase + (size_t)qm * SS + kn]     = v0;
                attn[abase + (size_t)qm * SS + kn + 1] = v1;
            }
        }
    }
}

// ---------------------------------------------------------------------------
// Row softmax over the first (q+1) entries.
// ---------------------------------------------------------------------------
__global__ __launch_bounds__(256) void softmax_rows(float* __restrict__ attn)
{
    const size_t row = blockIdx.x;
    const int q = (int)(row % SS);
    const int n = q + 1;
    float* p = attn + row * SS;
    const int t = threadIdx.x;

    __shared__ float redm[8];
    __shared__ float reds[8];

    float m = -1e30f;
    for (int i = t; i < n; i += 256) m = fmaxf(m, p[i]);
#pragma unroll
    for (int o = 16; o; o >>= 1) m = fmaxf(m, __shfl_xor_sync(0xffffffffu, m, o));
    if ((t & 31) == 0) redm[t >> 5] = m;
    __syncthreads();
    float bm = redm[0];
#pragma unroll
    for (int w = 1; w < 8; w++) bm = fmaxf(bm, redm[w]);

    float s = 0.f;
    for (int i = t; i < n; i += 256) {
        const float e = __expf(p[i] - bm);
        p[i] = e;
        s += e;
    }
#pragma unroll
    for (int o = 16; o; o >>= 1) s += __shfl_xor_sync(0xffffffffu, s, o);
    if ((t & 31) == 0) reds[t >> 5] = s;
    __syncthreads();
    float bs = reds[0];
#pragma unroll
    for (int w = 1; w < 8; w++) bs += reds[w];
    const float inv = 1.0f / bs;

    for (int i = t; i < n; i += 256) p[i] *= inv;
}

// ---------------------------------------------------------------------------
// ctx[b,q,h*64+c] = sum_k attn[bh,q,k] * V[bh,k,c]  via tf32 mma.
// Block tile 128q x 64c, BK=16; 8 warps (4m x 2n), warp tile 32x32.
// ---------------------------------------------------------------------------
__global__ __launch_bounds__(256) void attn_ctx_tf32(
    const float* __restrict__ attn, const float* __restrict__ Vh,
    float* __restrict__ ctx)
{
    const int tq = blockIdx.x;
    const int bh = blockIdx.y;
    const int bb = bh / HH, h = bh % HH;
    const int t  = threadIdx.x;

    __shared__ uint32_t As[128][20];
    __shared__ uint32_t Vs[16][68];

    const float* arow = attn + ((size_t)bh * SS + (size_t)tq * 128) * SS;
    const float* Vb   = Vh + (size_t)bh * SS * DEPTH;

    const int wid = t >> 5, lane = t & 31;
    const int wm  = (wid >> 1) * 32;     // 4 warps along m
    const int wn  = (wid & 1) * 32;      // 2 warps along n
    const int g   = lane >> 2, tg = lane & 3;

    float acc[2][4][4];
#pragma unroll
    for (int i = 0; i < 2; i++)
#pragma unroll
        for (int j = 0; j < 4; j++)
#pragma unroll
            for (int r = 0; r < 4; r++) acc[i][j][r] = 0.f;

    const int stages = (tq + 1) * 8;      // (tq+1)*128 keys / BK=16
    for (int s = 0; s < stages; s++) {
        const int kglob = s * 16;
#pragma unroll
        for (int i = 0; i < 2; i++) {     // attn tile 128x16
            const int f   = t * 2 + i;
            const int row = f >> 2;
            const int kq  = (f & 3) * 4;
            float4 av = *(const float4*)&arow[(size_t)row * SS + kglob + kq];
            uint4 au = make_uint4(f2tf(av.x), f2tf(av.y), f2tf(av.z), f2tf(av.w));
            *(uint4*)&As[row][kq] = au;
        }
        {                                  // V tile 16x64
            const int kk = t >> 4;
            const int c4 = (t & 15) * 4;
            float4 vv = *(const float4*)&Vb[(size_t)(kglob + kk) * DEPTH + c4];
            uint4 vu = make_uint4(f2tf(vv.x), f2tf(vv.y), f2tf(vv.z), f2tf(vv.w));
            *(uint4*)&Vs[kk][c4] = vu;
        }
        __syncthreads();

#pragma unroll
        for (int ks = 0; ks < 16; ks += 8) {
            uint32_t a[2][4], b[4][2];
#pragma unroll
            for (int i = 0; i < 2; i++) {
                const int r = wm + i * 16;
                a[i][0] = As[r + g][ks + tg];
                a[i][1] = As[r + g + 8][ks + tg];
                a[i][2] = As[r + g][ks + tg + 4];
                a[i][3] = As[r + g + 8][ks + tg + 4];
            }
#pragma unroll
            for (int j = 0; j < 4; j++) {
                const int n = wn + j * 8;
                b[j][0] = Vs[ks + tg][n + g];
                b[j][1] = Vs[ks + tg + 4][n + g];
            }
#pragma unroll
            for (int i = 0; i < 2; i++)
#pragma unroll
                for (int j = 0; j < 4; j++)
                    mma_tf32(acc[i][j], a[i], b[j]);
        }
        __syncthreads();
    }

#pragma unroll
    for (int i = 0; i < 2; i++) {
#pragma unroll
        for (int j = 0; j < 4; j++) {
            const int c = wn + j * 8 + 2 * tg;
#pragma unroll
            for (int half = 0; half < 2; half++) {
                const int q = tq * 128 + wm + i * 16 + g + half * 8;
                float* dst = &ctx[((size_t)bb * SS + q) * DD + h * DEPTH + c];
                dst[0] = acc[i][j][half * 2 + 0];
                dst[1] = acc[i][j][half * 2 + 1];
            }
        }
    }
}

// ---------------------------------------------------------------------------
extern "C" void kernel_launch(void* const* d_in, const int* in_sizes, int n_in,
                              void* d_out, int out_size)
{
    const float* q    = (const float*)d_in[0];
    const float* k    = (const float*)d_in[1];
    const float* v    = (const float*)d_in[2];
    // d_in[3] = mask (causal; applied analytically)
    const float* wq   = (const float*)d_in[4];
    const float* bq   = (const float*)d_in[5];
    const float* wk   = (const float*)d_in[6];
    const float* bk   = (const float*)d_in[7];
    const float* wv   = (const float*)d_in[8];
    const float* bv   = (const float*)d_in[9];
    const float* wo   = (const float*)d_in[10];
    const float* bo   = (const float*)d_in[11];
    float* out = (float*)d_out;

    float *gq, *gk, *gv, *gctx, *gattn;
    cudaGetSymbolAddress((void**)&gq,   g_q);
    cudaGetSymbolAddress((void**)&gk,   g_k);
    cudaGetSymbolAddress((void**)&gv,   g_v);
    cudaGetSymbolAddress((void**)&gctx, g_ctx);
    cudaGetSymbolAddress((void**)&gattn, g_attn_fb);

    const long long OUT_E = (long long)BB * SS * DD;
    const long long ATT_E = (long long)BB * HH * SS * SS;
    float* attn = ((long long)out_size >= OUT_E + ATT_E) ? (out + OUT_E) : gattn;

    const dim3 gproj(DD / 128, MTOT / 128);

    proj_tf32<<<gproj, 256>>>(q, wq, bq, gq, MTOT, DD, DD, 1);
    proj_tf32<<<gproj, 256>>>(k, wk, bk, gk, MTOT, DD, DD, 1);
    proj_tf32<<<gproj, 256>>>(v, wv, bv, gv, MTOT, DD, DD, 1);

    attn_logits_tf32<<<dim3(SS / 128, SS / 128, BB * HH), 256>>>(gq, gk, attn);
    softmax_rows<<<BB * HH * SS, 256>>>(attn);
    attn_ctx_tf32<<<dim3(SS / 128, BB * HH), 256>>>(attn, gv, gctx);

    proj_tf32<<<gproj, 256>>>(gctx, wo, bo, out, MTOT, DD, DD, 0);
}